// round 5
// baseline (speedup 1.0000x reference)
#include <cuda_runtime.h>

// RandomSelfAttention: B=2, S=4096, S2=2048, NH=8, H=64, NKEYS=64
// q (B,S2,NH,H) f32 | k (B,S,NH,H) f32 | v (B,S,NH,H) f32 | indices (B,S2,NKEYS) int32-or-int64
// Output: z (B,S2,NH,H) f32

#define SKEYS 4096
#define SQ    2048
#define NH    8
#define H     64
#define NKEYS 64

__global__ void __launch_bounds__(256, 8) rsa_kernel(
    const float* __restrict__ q,
    const float* __restrict__ k,
    const float* __restrict__ v,
    const void*  __restrict__ idx_raw,
    float* __restrict__ out)
{
    __shared__ int   s_idx[NKEYS];
    __shared__ float s_scores[NH][NKEYS];
    __shared__ int   s_is64;

    const int bq   = blockIdx.x;          // 0 .. B*SQ-1 ; one (batch, query) per CTA
    const int tid  = threadIdx.x;
    const int head = tid >> 5;            // warp == head
    const int lane = tid & 31;

    // ---- Index dtype detection: indices < 4096, so int64 data has every odd
    // 32-bit word == 0. Probe the first 64 odd words (same address for all
    // CTAs -> L2 broadcast).
    if (tid == 0) s_is64 = 1;
    __syncthreads();
    const int* i32 = (const int*)idx_raw;
    if (tid < NKEYS) {
        if (i32[2 * tid + 1] != 0) atomicExch(&s_is64, 0);
    }
    __syncthreads();

    // ---- Stage the 64 shared indices as int32
    if (tid < NKEYS) {
        const long long off = (long long)bq * NKEYS + tid;
        s_idx[tid] = s_is64 ? (int)((const long long*)idx_raw)[off] : i32[off];
    }
    __syncthreads();

    // Each lane owns 2 consecutive head-dims: d = 2*lane, 2*lane+1
    const float* qp = q + ((long long)bq * NH + head) * H;
    float2 qv = *(const float2*)(qp + 2 * lane);
    qv.x *= 0.125f;   // H^-0.5 = 1/8
    qv.y *= 0.125f;

    const long long b  = bq / SQ;
    const float* kb = k + b * (long long)SKEYS * NH * H;
    const float* vb = v + b * (long long)SKEYS * NH * H;

    // ---- Phase 1: scores A[j] = (q/sqrt(H)) . k_gather[j]  (64 keys) ----
    #pragma unroll 4
    for (int j = 0; j < NKEYS; ++j) {
        const int idx = s_idx[j];
        const float2 kv = *(const float2*)(kb + ((long long)idx * NH + head) * H + 2 * lane);
        float p = fmaf(qv.x, kv.x, qv.y * kv.y);
        #pragma unroll
        for (int off = 16; off; off >>= 1)
            p += __shfl_xor_sync(0xffffffffu, p, off);
        if (lane == 0) s_scores[head][j] = p;
    }
    __syncwarp();

    // ---- Phase 2: softmax over the 64 gathered keys (2 per lane) ----
    float s0 = s_scores[head][lane];
    float s1 = s_scores[head][lane + 32];
    float m = fmaxf(s0, s1);
    #pragma unroll
    for (int off = 16; off; off >>= 1)
        m = fmaxf(m, __shfl_xor_sync(0xffffffffu, m, off));
    float e0 = __expf(s0 - m);
    float e1 = __expf(s1 - m);
    float sum = e0 + e1;
    #pragma unroll
    for (int off = 16; off; off >>= 1)
        sum += __shfl_xor_sync(0xffffffffu, sum, off);
    const float inv = 1.0f / sum;
    s_scores[head][lane]      = e0 * inv;
    s_scores[head][lane + 32] = e1 * inv;
    __syncwarp();

    // ---- Phase 3: z = sum_j p[j] * v_gather[j] ----
    float2 acc = make_float2(0.0f, 0.0f);
    #pragma unroll 4
    for (int j = 0; j < NKEYS; ++j) {
        const float p   = s_scores[head][j];      // same-address broadcast read
        const int   idx = s_idx[j];
        const float2 vv = *(const float2*)(vb + ((long long)idx * NH + head) * H + 2 * lane);
        acc.x = fmaf(p, vv.x, acc.x);
        acc.y = fmaf(p, vv.y, acc.y);
    }

    float* op = out + ((long long)bq * NH + head) * H;
    *(float2*)(op + 2 * lane) = acc;
}

extern "C" void kernel_launch(void* const* d_in, const int* in_sizes, int n_in,
                              void* d_out, int out_size) {
    // Identify inputs by element count (robust to metadata ordering):
    //   q   = B*S2*NH*H = 2,097,152
    //   k,v = B*S *NH*H = 4,194,304 (k assumed before v)
    //   idx = B*S2*NKEYS =  262,144
    const float* q = nullptr;
    const float* k = nullptr;
    const float* v = nullptr;
    const void*  idx = nullptr;
    for (int i = 0; i < n_in; ++i) {
        if (in_sizes[i] == 2097152)      q = (const float*)d_in[i];
        else if (in_sizes[i] == 262144)  idx = d_in[i];
        else if (in_sizes[i] == 4194304) {
            if (!k) k = (const float*)d_in[i];
            else    v = (const float*)d_in[i];
        }
    }
    float* out = (float*)d_out;

    rsa_kernel<<<2 * SQ, 256>>>(q, k, v, idx, out);
}

// round 6
// speedup vs baseline: 2.2545x; 2.2545x over previous
#include <cuda_runtime.h>

// RandomSelfAttention: B=2, S=4096, S2=2048, NH=8, H=64, NKEYS=64
// q (B,S2,NH,H) f32 | k (B,S,NH,H) f32 | v (B,S,NH,H) f32 | indices (B,S2,NKEYS)
// Output: z (B,S2,NH,H) f32
//
// One CTA per (batch,query); warp == head. Within a warp, 16 lanes per key row
// (float4/lane), 2 keys per iteration -> half the LDGs, 2 shfls/key instead of 5.

#define SKEYS 4096
#define SQ    2048
#define NH    8
#define H     64
#define NKEYS 64

__global__ void __launch_bounds__(256, 8) rsa_kernel(
    const float* __restrict__ q,
    const float* __restrict__ k,
    const float* __restrict__ v,
    const void*  __restrict__ idx_raw,
    float* __restrict__ out)
{
    __shared__ int2  s_off2[NKEYS / 2];     // element offsets (idx*NH*H), pairs
    __shared__ float s_p[NH][NKEYS];        // scores -> probabilities
    __shared__ int   s_is64;

    const int bq   = blockIdx.x;            // one (batch, query) per CTA
    const int tid  = threadIdx.x;
    const int head = tid >> 5;
    const int lane = tid & 31;
    const int hl   = lane & 15;             // lane within half-warp
    const int hi   = lane >> 4;             // 0: even key, 1: odd key

    // ---- Index dtype detection: values < 4096, so int64 data has every odd
    // 32-bit word zero. Probe 64 odd words (same address all CTAs -> L2 bcast).
    if (tid == 0) s_is64 = 1;
    __syncthreads();
    const int* i32 = (const int*)idx_raw;
    if (tid < NKEYS) {
        if (i32[2 * tid + 1] != 0) atomicExch(&s_is64, 0);
    }
    __syncthreads();

    // ---- Stage pre-scaled element offsets: off = idx * NH*H = idx << 9
    if (tid < NKEYS / 2) {
        const long long base = (long long)bq * NKEYS + 2 * tid;
        int i0, i1;
        if (s_is64) {
            i0 = (int)((const long long*)idx_raw)[base];
            i1 = (int)((const long long*)idx_raw)[base + 1];
        } else {
            i0 = i32[base];
            i1 = i32[base + 1];
        }
        s_off2[tid] = make_int2(i0 << 9, i1 << 9);
    }
    __syncthreads();

    // Per-warp base pointers with head + lane-dim folded in
    const long long b = bq / SQ;
    const int dimoff  = (head << 6) + 4 * hl;           // head*H + 4*(lane&15)
    const float* kbh  = k + b * (long long)SKEYS * NH * H + dimoff;
    const float* vbh  = v + b * (long long)SKEYS * NH * H + dimoff;

    // q: each half-warp loads the same 64 floats (broadcast), scale by 1/8
    const float* qp = q + ((long long)bq * NH + head) * H + 4 * hl;
    float4 qv = *(const float4*)qp;
    qv.x *= 0.125f; qv.y *= 0.125f; qv.z *= 0.125f; qv.w *= 0.125f;

    // ---- Phase 1: scores (2 keys / iteration) ----
    #pragma unroll 8
    for (int j = 0; j < NKEYS / 2; ++j) {
        const int2 o2 = s_off2[j];
        const int  o  = hi ? o2.y : o2.x;
        const float4 kk = *(const float4*)(kbh + o);
        float p = qv.x * kk.x + qv.y * kk.y + qv.z * kk.z + qv.w * kk.w;
        #pragma unroll
        for (int off = 8; off; off >>= 1)
            p += __shfl_xor_sync(0xffffffffu, p, off);
        if (hl == 0) s_p[head][2 * j + hi] = p;         // lanes 0 and 16 write
    }
    __syncwarp();

    // ---- Phase 2: softmax over 64 keys (2 per lane) ----
    float s0 = s_p[head][lane];
    float s1 = s_p[head][lane + 32];
    float m = fmaxf(s0, s1);
    #pragma unroll
    for (int off = 16; off; off >>= 1)
        m = fmaxf(m, __shfl_xor_sync(0xffffffffu, m, off));
    float e0 = __expf(s0 - m);
    float e1 = __expf(s1 - m);
    float sum = e0 + e1;
    #pragma unroll
    for (int off = 16; off; off >>= 1)
        sum += __shfl_xor_sync(0xffffffffu, sum, off);
    const float inv = 1.0f / sum;
    s_p[head][lane]      = e0 * inv;
    s_p[head][lane + 32] = e1 * inv;
    __syncwarp();

    // ---- Phase 3: z = sum_j p[j] * v[idx_j]  (2 keys / iteration) ----
    float4 acc = make_float4(0.f, 0.f, 0.f, 0.f);
    #pragma unroll 8
    for (int j = 0; j < NKEYS / 2; ++j) {
        const float2 pp = *(const float2*)&s_p[head][2 * j];   // broadcast
        const float  p  = hi ? pp.y : pp.x;
        const int2   o2 = s_off2[j];
        const int    o  = hi ? o2.y : o2.x;
        const float4 vv = *(const float4*)(vbh + o);
        acc.x = fmaf(p, vv.x, acc.x);
        acc.y = fmaf(p, vv.y, acc.y);
        acc.z = fmaf(p, vv.z, acc.z);
        acc.w = fmaf(p, vv.w, acc.w);
    }

    // Combine even-key (lanes 0-15) and odd-key (lanes 16-31) partials
    acc.x += __shfl_xor_sync(0xffffffffu, acc.x, 16);
    acc.y += __shfl_xor_sync(0xffffffffu, acc.y, 16);
    acc.z += __shfl_xor_sync(0xffffffffu, acc.z, 16);
    acc.w += __shfl_xor_sync(0xffffffffu, acc.w, 16);

    if (hi == 0) {
        float* op = out + ((long long)bq * NH + head) * H + 4 * hl;
        *(float4*)op = acc;
    }
}

extern "C" void kernel_launch(void* const* d_in, const int* in_sizes, int n_in,
                              void* d_out, int out_size) {
    // Identify inputs by element count (robust to metadata ordering):
    //   q = 2,097,152 | k,v = 4,194,304 (k before v) | idx = 262,144
    const float* q = nullptr;
    const float* k = nullptr;
    const float* v = nullptr;
    const void*  idx = nullptr;
    for (int i = 0; i < n_in; ++i) {
        if (in_sizes[i] == 2097152)      q = (const float*)d_in[i];
        else if (in_sizes[i] == 262144)  idx = d_in[i];
        else if (in_sizes[i] == 4194304) {
            if (!k) k = (const float*)d_in[i];
            else    v = (const float*)d_in[i];
        }
    }
    float* out = (float*)d_out;

    rsa_kernel<<<2 * SQ, 256>>>(q, k, v, idx, out);
}

// round 9
// speedup vs baseline: 2.8192x; 1.2505x over previous
#include <cuda_runtime.h>

// RandomSelfAttention: B=2, S=4096, S2=2048, NH=8, H=64, NKEYS=64
// q (B,S2,NH,H) f32 | k (B,S,NH,H) f32 | v (B,S,NH,H) f32 | indices (B,S2,NKEYS)
// Output: z (B,S2,NH,H) f32
//
// One CTA per (batch,query); warp == head.
// Phase 1: 8 lanes/key, 4 keys/iter -> 3 shfls per 4 keys, fully coalesced LDG.128.
// Phase 3: 16 lanes/key, 4 keys/iter, packed LDS.128 for offsets & probs.

#define SKEYS 4096
#define SQ    2048
#define NH    8
#define H     64
#define NKEYS 64
#define KVSTRIDE (NH * H)   // 512 elements per sequence position

__global__ void __launch_bounds__(256, 6) rsa_kernel(
    const float* __restrict__ q,
    const float* __restrict__ k,
    const float* __restrict__ v,
    const void*  __restrict__ idx_raw,
    float* __restrict__ out)
{
    __shared__ int4  s_off4[NKEYS / 4];    // element offsets (idx<<9), quads
    __shared__ float s_sc[NH][NKEYS];      // raw scores
    __shared__ float s_p[NH][NKEYS];       // probabilities (quad-readable)
    __shared__ int   s_is64;

    const int bq   = blockIdx.x;           // one (batch, query) per CTA
    const int tid  = threadIdx.x;
    const int head = tid >> 5;
    const int lane = tid & 31;

    // ---- Index dtype detection: values < 4096, so int64 data has every odd
    // 32-bit word zero. Probe 64 odd words (same address all CTAs -> L2 bcast).
    if (tid == 0) s_is64 = 1;
    __syncthreads();
    const int* i32 = (const int*)idx_raw;
    if (tid < NKEYS) {
        if (i32[2 * tid + 1] != 0) atomicExch(&s_is64, 0);
    }
    __syncthreads();

    // ---- Stage pre-scaled element offsets as int4 quads: off = idx << 9
    if (tid < NKEYS / 4) {
        const long long base = (long long)bq * NKEYS + 4 * tid;
        int4 r;
        if (s_is64) {
            const long long* i64 = (const long long*)idx_raw;
            r.x = (int)i64[base];     r.y = (int)i64[base + 1];
            r.z = (int)i64[base + 2]; r.w = (int)i64[base + 3];
        } else {
            r = *(const int4*)(i32 + base);
        }
        r.x <<= 9; r.y <<= 9; r.z <<= 9; r.w <<= 9;
        s_off4[tid] = r;
    }
    __syncthreads();

    const long long b = bq / SQ;
    const float* kvbase_k = k + b * (long long)SKEYS * KVSTRIDE + (head << 6);
    const float* kvbase_v = v + b * (long long)SKEYS * KVSTRIDE + (head << 6);

    // ================= Phase 1: scores, 8 lanes/key, 4 keys/iter =============
    {
        const int g  = lane >> 3;          // key group 0..3
        const int sl = lane & 7;           // sub-lane: dims [4sl,4sl+4) & [32+4sl,+4)
        const float* kb_l = kvbase_k + 4 * sl;

        const float* qp = q + ((long long)bq * NH + head) * H;
        float4 qa = *(const float4*)(qp + 4 * sl);
        float4 qb = *(const float4*)(qp + 32 + 4 * sl);
        qa.x *= 0.125f; qa.y *= 0.125f; qa.z *= 0.125f; qa.w *= 0.125f;
        qb.x *= 0.125f; qb.y *= 0.125f; qb.z *= 0.125f; qb.w *= 0.125f;

        #pragma unroll 4
        for (int j = 0; j < NKEYS / 4; ++j) {
            const int4 o4 = s_off4[j];                       // broadcast LDS.128
            const int o = (g & 2) ? ((g & 1) ? o4.w : o4.z)
                                  : ((g & 1) ? o4.y : o4.x);
            const float4 ka = *(const float4*)(kb_l + o);        // dims [4sl,+4)
            const float4 kc = *(const float4*)(kb_l + o + 32);   // dims [32+4sl,+4)
            float p = qa.x * ka.x + qa.y * ka.y + qa.z * ka.z + qa.w * ka.w
                    + qb.x * kc.x + qb.y * kc.y + qb.z * kc.z + qb.w * kc.w;
            p += __shfl_xor_sync(0xffffffffu, p, 4);
            p += __shfl_xor_sync(0xffffffffu, p, 2);
            p += __shfl_xor_sync(0xffffffffu, p, 1);
            if (sl == 0) s_sc[head][4 * j + g] = p;
        }
    }
    __syncwarp();

    // ================= Phase 2: softmax over 64 keys (2 per lane) ============
    {
        float s0 = s_sc[head][lane];
        float s1 = s_sc[head][lane + 32];
        float m = fmaxf(s0, s1);
        #pragma unroll
        for (int off = 16; off; off >>= 1)
            m = fmaxf(m, __shfl_xor_sync(0xffffffffu, m, off));
        float e0 = __expf(s0 - m);
        float e1 = __expf(s1 - m);
        float sum = e0 + e1;
        #pragma unroll
        for (int off = 16; off; off >>= 1)
            sum += __shfl_xor_sync(0xffffffffu, sum, off);
        const float inv = 1.0f / sum;
        s_p[head][lane]      = e0 * inv;
        s_p[head][lane + 32] = e1 * inv;
    }
    __syncwarp();

    // ================= Phase 3: z = sum_j p[j]*v[idx_j], 4 keys/iter =========
    {
        const int hl = lane & 15;          // lane owns dims [4hl, 4hl+4)
        const int hi = lane >> 4;          // half 0: keys 4j,4j+1; half 1: 4j+2,4j+3
        const float* vb_l = kvbase_v + 4 * hl;

        float4 acc = make_float4(0.f, 0.f, 0.f, 0.f);
        #pragma unroll 4
        for (int j = 0; j < NKEYS / 4; ++j) {
            const int4   o4 = s_off4[j];                       // broadcast LDS.128
            const float4 p4 = *(const float4*)&s_p[head][4 * j];
            const int   oa = hi ? o4.z : o4.x;
            const int   ob = hi ? o4.w : o4.y;
            const float pa = hi ? p4.z : p4.x;
            const float pb = hi ? p4.w : p4.y;
            const float4 va = *(const float4*)(vb_l + oa);
            const float4 vc = *(const float4*)(vb_l + ob);
            acc.x = fmaf(pa, va.x, fmaf(pb, vc.x, acc.x));
            acc.y = fmaf(pa, va.y, fmaf(pb, vc.y, acc.y));
            acc.z = fmaf(pa, va.z, fmaf(pb, vc.z, acc.z));
            acc.w = fmaf(pa, va.w, fmaf(pb, vc.w, acc.w));
        }

        // Combine the two half-warps' key partials
        acc.x += __shfl_xor_sync(0xffffffffu, acc.x, 16);
        acc.y += __shfl_xor_sync(0xffffffffu, acc.y, 16);
        acc.z += __shfl_xor_sync(0xffffffffu, acc.z, 16);
        acc.w += __shfl_xor_sync(0xffffffffu, acc.w, 16);

        if (hi == 0) {
            float* op = out + ((long long)bq * NH + head) * H + 4 * hl;
            *(float4*)op = acc;
        }
    }
}

extern "C" void kernel_launch(void* const* d_in, const int* in_sizes, int n_in,
                              void* d_out, int out_size) {
    // Identify inputs by element count (robust to metadata ordering):
    //   q = 2,097,152 | k,v = 4,194,304 (k before v) | idx = 262,144
    const float* q = nullptr;
    const float* k = nullptr;
    const float* v = nullptr;
    const void*  idx = nullptr;
    for (int i = 0; i < n_in; ++i) {
        if (in_sizes[i] == 2097152)      q = (const float*)d_in[i];
        else if (in_sizes[i] == 262144)  idx = d_in[i];
        else if (in_sizes[i] == 4194304) {
            if (!k) k = (const float*)d_in[i];
            else    v = (const float*)d_in[i];
        }
    }
    float* out = (float*)d_out;

    rsa_kernel<<<2 * SQ, 256>>>(q, k, v, idx, out);
}